// round 1
// baseline (speedup 1.0000x reference)
#include <cuda_runtime.h>
#include <cstdint>

// ---------------------------------------------------------------------------
// YOLOv2 head: conv3x3(512->1024)+BN+LeakyReLU -> conv1x1(1024->425)+bias ->
// decode (sigmoid/exp/softmax-max/argmax -> boxes+scores+labels)
// fp32 baseline using packed fma.rn.f32x2 (FFMA2) for 2x fp32 FMA rate.
// ---------------------------------------------------------------------------

static constexpr int S_ = 32;          // spatial
static constexpr int CIN_ = 512;
static constexpr int CMID_ = 1024;
static constexpr int CO2_ = 425;       // 5 * (5 + 80)
static constexpr int NPOS_ = S_ * S_;  // 1024

// Scratch (device globals: allocation-free scratch per harness rules)
__device__ float g_x[(size_t)32 * CMID_ * NPOS_];      // (B, 1024, 32, 32) post BN+leaky
__device__ float g_preds[(size_t)32 * CO2_ * NPOS_];   // (B, 425, 32, 32)

__constant__ float c_anc_w[5] = {42.f, 98.f, 180.f, 300.f, 400.f};
__constant__ float c_anc_h[5] = {45.f, 130.f, 260.f, 180.f, 400.f};

__device__ __forceinline__ void ffma2(unsigned long long& d,
                                      unsigned long long a,
                                      unsigned long long b) {
    asm("fma.rn.f32x2 %0, %1, %2, %3;" : "=l"(d) : "l"(a), "l"(b), "l"(d));
}

__device__ __forceinline__ float lo_f(unsigned long long v) {
    return __uint_as_float((unsigned)(v & 0xffffffffull));
}
__device__ __forceinline__ float hi_f(unsigned long long v) {
    return __uint_as_float((unsigned)(v >> 32));
}

// ---------------------------------------------------------------------------
// conv1: 3x3, pad 1, 512->1024, fused BN + LeakyReLU(0.1).
// Block: 64 output channels x (8 rows x 32 cols) for one batch.
// Grid: (4 row tiles, 16 co tiles, 32 batches).
// Thread (256): ct = tid&7 -> 8 co (as 4 f32x2 pairs); pt = tid>>3 -> 8 pos.
// ---------------------------------------------------------------------------
__global__ __launch_bounds__(256, 2)
void conv1_bn_lrelu(const float* __restrict__ feat,
                    const float* __restrict__ w1,
                    const float* __restrict__ gamma,
                    const float* __restrict__ beta,
                    const float* __restrict__ mean,
                    const float* __restrict__ var) {
    __shared__ __align__(16) float2 sIn[8][10][34];   // input, duplicated {v,v}; halo'd
    __shared__ __align__(16) float  sW[8][9][80];     // [ci][kh*3+kw][co], pad 64->80

    const int b    = blockIdx.z;
    const int co0  = blockIdx.y * 64;
    const int row0 = blockIdx.x * 8;
    const int tid  = threadIdx.x;
    const int ct   = tid & 7;
    const int pt   = tid >> 3;
    const int r    = pt >> 2;          // 0..7 output row within tile
    const int cb   = (pt & 3) * 8;     // output col block (8 consecutive cols)

    unsigned long long acc[4][8];
#pragma unroll
    for (int j = 0; j < 4; j++)
#pragma unroll
        for (int c = 0; c < 8; c++) acc[j][c] = 0ull;

    const float* featb = feat + (size_t)b * CIN_ * NPOS_;

    for (int ci0 = 0; ci0 < CIN_; ci0 += 8) {
        // ---- load input tile (8 ci x 10 rows x 34 cols, zero-padded halo) ----
#pragma unroll
        for (int it = 0; it < 11; it++) {
            int i = tid + it * 256;
            if (i < 8 * 10 * 34) {
                int k   = i / 340;
                int rem = i - k * 340;
                int gr  = rem / 34;
                int gc  = rem - gr * 34;
                int gh  = row0 + gr - 1;
                int gw  = gc - 1;
                float v = 0.f;
                if ((unsigned)gh < 32u && (unsigned)gw < 32u)
                    v = featb[((ci0 + k) * S_ + gh) * S_ + gw];
                sIn[k][gr][gc] = make_float2(v, v);
            }
        }
        // ---- load weights (64 co x 8 ci x 9) ----
#pragma unroll
        for (int it = 0; it < 18; it++) {
            int i   = tid + it * 256;          // exactly 4608 = 18*256
            int co  = i / 72;
            int rem = i - co * 72;
            int k   = rem / 9;
            int kk  = rem - k * 9;
            sW[k][kk][co] =
                w1[((size_t)(co0 + co) * CIN_ + (ci0 + k)) * 9 + kk];
        }
        __syncthreads();

        // ---- compute ----
#pragma unroll 2
        for (int k = 0; k < 8; k++) {
#pragma unroll
            for (int kh = 0; kh < 3; kh++) {
                const unsigned long long* inrow =
                    reinterpret_cast<const unsigned long long*>(&sIn[k][r + kh][0]);
                unsigned long long iv[10];
#pragma unroll
                for (int i = 0; i < 10; i++) iv[i] = inrow[cb + i];
#pragma unroll
                for (int kw = 0; kw < 3; kw++) {
                    const int kk = kh * 3 + kw;
                    const ulonglong2* wp =
                        reinterpret_cast<const ulonglong2*>(&sW[k][kk][ct * 8]);
                    ulonglong2 w01 = wp[0];
                    ulonglong2 w23 = wp[1];
#pragma unroll
                    for (int c = 0; c < 8; c++) {
                        unsigned long long in2 = iv[kw + c];
                        ffma2(acc[0][c], w01.x, in2);
                        ffma2(acc[1][c], w01.y, in2);
                        ffma2(acc[2][c], w23.x, in2);
                        ffma2(acc[3][c], w23.y, in2);
                    }
                }
            }
        }
        __syncthreads();
    }

    // ---- epilogue: BN + leaky, vectorized stores ----
    float* outb = g_x + (size_t)b * CMID_ * NPOS_ + (size_t)(row0 + r) * S_ + cb;
#pragma unroll
    for (int j = 0; j < 4; j++) {
#pragma unroll
        for (int h = 0; h < 2; h++) {
            int co = co0 + ct * 8 + j * 2 + h;
            float sc = gamma[co] * rsqrtf(var[co] + 1e-5f);
            float sh = beta[co] - mean[co] * sc;
            float vals[8];
#pragma unroll
            for (int c = 0; c < 8; c++) {
                unsigned long long a = acc[j][c];
                float v = (h == 0 ? lo_f(a) : hi_f(a)) * sc + sh;
                vals[c] = v > 0.f ? v : 0.1f * v;
            }
            float* o = outb + (size_t)co * NPOS_;
            *reinterpret_cast<float4*>(o) =
                make_float4(vals[0], vals[1], vals[2], vals[3]);
            *reinterpret_cast<float4*>(o + 4) =
                make_float4(vals[4], vals[5], vals[6], vals[7]);
        }
    }
}

// ---------------------------------------------------------------------------
// conv2: 1x1, 1024 -> 425 (+bias). SGEMM per batch:
// preds[b][co][p] = sum_ci w2[co][ci] * x[b][ci][p] + b2[co]
// Tile 128(co) x 128(pos) x 8(K). Thread: 8 co (4 pairs) x 8 pos.
// ---------------------------------------------------------------------------
__global__ __launch_bounds__(256, 2)
void conv2_gemm(const float* __restrict__ w2, const float* __restrict__ b2) {
    __shared__ __align__(16) float  sA[8][132];      // [kk][co], padded
    __shared__ __align__(16) float2 sB[8][128];      // [kk][pos], duplicated {v,v}

    const int b   = blockIdx.z;
    const int co0 = blockIdx.y * 128;
    const int p0  = blockIdx.x * 128;
    const int tid = threadIdx.x;
    const int ct  = tid & 15;
    const int pt  = tid >> 4;

    unsigned long long acc[4][8];
#pragma unroll
    for (int j = 0; j < 4; j++)
#pragma unroll
        for (int c = 0; c < 8; c++) acc[j][c] = 0ull;

    const float* xb = g_x + (size_t)b * CMID_ * NPOS_;

    for (int ci0 = 0; ci0 < CMID_; ci0 += 8) {
        // sA: 1024 floats, one float4 per thread (coalesced along ci)
        {
            int co  = tid >> 1;
            int kk4 = (tid & 1) * 4;
            int cog = co0 + co;
            float4 v = make_float4(0.f, 0.f, 0.f, 0.f);
            if (cog < CO2_)
                v = *reinterpret_cast<const float4*>(
                    &w2[(size_t)cog * CMID_ + ci0 + kk4]);
            sA[kk4 + 0][co] = v.x;
            sA[kk4 + 1][co] = v.y;
            sA[kk4 + 2][co] = v.z;
            sA[kk4 + 3][co] = v.w;
        }
        // sB: 1024 floats, one float4 per thread (coalesced along pos)
        {
            int kk = tid >> 5;
            int pp = (tid & 31) * 4;
            float4 v = *reinterpret_cast<const float4*>(
                &xb[(size_t)(ci0 + kk) * NPOS_ + p0 + pp]);
            sB[kk][pp + 0] = make_float2(v.x, v.x);
            sB[kk][pp + 1] = make_float2(v.y, v.y);
            sB[kk][pp + 2] = make_float2(v.z, v.z);
            sB[kk][pp + 3] = make_float2(v.w, v.w);
        }
        __syncthreads();

#pragma unroll
        for (int kk = 0; kk < 8; kk++) {
            const ulonglong2* wp =
                reinterpret_cast<const ulonglong2*>(&sA[kk][ct * 8]);
            ulonglong2 w01 = wp[0];
            ulonglong2 w23 = wp[1];
            const unsigned long long* inrow =
                reinterpret_cast<const unsigned long long*>(&sB[kk][pt * 8]);
#pragma unroll
            for (int c = 0; c < 8; c++) {
                unsigned long long in2 = inrow[c];
                ffma2(acc[0][c], w01.x, in2);
                ffma2(acc[1][c], w01.y, in2);
                ffma2(acc[2][c], w23.x, in2);
                ffma2(acc[3][c], w23.y, in2);
            }
        }
        __syncthreads();
    }

    // epilogue: bias + store (guard co < 425)
#pragma unroll
    for (int j = 0; j < 4; j++) {
#pragma unroll
        for (int h = 0; h < 2; h++) {
            int co = co0 + ct * 8 + j * 2 + h;
            if (co < CO2_) {
                float bias = b2[co];
                float vals[8];
#pragma unroll
                for (int c = 0; c < 8; c++) {
                    unsigned long long a = acc[j][c];
                    vals[c] = (h == 0 ? lo_f(a) : hi_f(a)) + bias;
                }
                float* o = g_preds + ((size_t)b * CO2_ + co) * NPOS_ + p0 + pt * 8;
                *reinterpret_cast<float4*>(o) =
                    make_float4(vals[0], vals[1], vals[2], vals[3]);
                *reinterpret_cast<float4*>(o + 4) =
                    make_float4(vals[4], vals[5], vals[6], vals[7]);
            }
        }
    }
}

// ---------------------------------------------------------------------------
// decode: one thread per (b, p, a). Online softmax-max + argmax.
// Output layout: [out5 (32*5120*5 f32)] then [labels (32*5120) as f32].
// ---------------------------------------------------------------------------
__global__ void decode_kernel(float* __restrict__ out) {
    int t = blockIdx.x * 256 + threadIdx.x;      // 163840 total
    int p  = t & 1023;
    int ba = t >> 10;
    int a  = ba % 5;
    int b  = ba / 5;

    const float* pr = g_preds + ((size_t)b * CO2_ + a * 85) * NPOS_ + p;
    float tx = pr[0 * NPOS_];
    float ty = pr[1 * NPOS_];
    float tw = pr[2 * NPOS_];
    float th = pr[3 * NPOS_];
    float to = pr[4 * NPOS_];

    float m = -1e30f, ssum = 0.f;
    int arg = 0;
#pragma unroll 4
    for (int j = 0; j < 80; j++) {
        float l = pr[(5 + j) * NPOS_];
        if (l > m) {
            ssum = ssum * expf(m - l) + 1.f;
            m = l;
            arg = j;
        } else {
            ssum += expf(l - m);
        }
    }

    float obj   = 1.f / (1.f + expf(-to));
    float score = obj / ssum;                // obj * max(softmax)
    float bx = 1.f / (1.f + expf(-tx));
    float by = 1.f / (1.f + expf(-ty));
    float bw = expf(fminf(tw, 8.f));
    float bh = expf(fminf(th, 8.f));

    float sx = (float)(p & 31);
    float sy = (float)(p >> 5);
    float cx = (bx + sx) * 32.f;
    float cy = (by + sy) * 32.f;
    float pw = c_anc_w[a] * bw;              // (anchor/32)*exp*32
    float ph = c_anc_h[a] * bh;

    float x1 = fminf(fmaxf(cx - 0.5f * pw, 0.f), 1023.f);
    float y1 = fminf(fmaxf(cy - 0.5f * ph, 0.f), 1023.f);
    float x2 = fminf(fmaxf(cx + 0.5f * pw, 0.f), 1023.f);
    float y2 = fminf(fmaxf(cy + 0.5f * ph, 0.f), 1023.f);

    size_t n = (size_t)b * 5120 + (size_t)p * 5 + a;
    float* o5 = out + n * 5;
    o5[0] = x1;
    o5[1] = y1;
    o5[2] = x2;
    o5[3] = y2;
    o5[4] = score;
    out[(size_t)819200 + n] = (float)arg;
}

// ---------------------------------------------------------------------------
extern "C" void kernel_launch(void* const* d_in, const int* in_sizes, int n_in,
                              void* d_out, int out_size) {
    const float* feat  = (const float*)d_in[0];
    const float* w1    = (const float*)d_in[1];
    const float* gam   = (const float*)d_in[2];
    const float* bet   = (const float*)d_in[3];
    const float* mean  = (const float*)d_in[4];
    const float* var   = (const float*)d_in[5];
    const float* w2    = (const float*)d_in[6];
    const float* b2    = (const float*)d_in[7];
    float* out = (float*)d_out;

    conv1_bn_lrelu<<<dim3(4, 16, 32), 256>>>(feat, w1, gam, bet, mean, var);
    conv2_gemm<<<dim3(8, 4, 32), 256>>>(w2, b2);
    decode_kernel<<<640, 256>>>(out);
}

// round 2
// speedup vs baseline: 1.0038x; 1.0038x over previous
#include <cuda_runtime.h>
#include <cstdint>

// ---------------------------------------------------------------------------
// YOLOv2 head: conv3x3(512->1024)+BN+LeakyReLU -> conv1x1(1024->425)+bias ->
// decode (sigmoid/exp/softmax-max/argmax -> boxes+scores+labels)
// fp32 baseline using packed fma.rn.f32x2 (FFMA2) for 2x fp32 FMA rate.
// ---------------------------------------------------------------------------

static constexpr int S_ = 32;          // spatial
static constexpr int CIN_ = 512;
static constexpr int CMID_ = 1024;
static constexpr int CO2_ = 425;       // 5 * (5 + 80)
static constexpr int NPOS_ = S_ * S_;  // 1024

// Scratch (device globals: allocation-free scratch per harness rules)
__device__ float g_x[(size_t)32 * CMID_ * NPOS_];      // (B, 1024, 32, 32) post BN+leaky
__device__ float g_preds[(size_t)32 * CO2_ * NPOS_];   // (B, 425, 32, 32)

__constant__ float c_anc_w[5] = {42.f, 98.f, 180.f, 300.f, 400.f};
__constant__ float c_anc_h[5] = {45.f, 130.f, 260.f, 180.f, 400.f};

__device__ __forceinline__ void ffma2(unsigned long long& d,
                                      unsigned long long a,
                                      unsigned long long b) {
    asm("fma.rn.f32x2 %0, %1, %2, %3;" : "=l"(d) : "l"(a), "l"(b), "l"(d));
}

__device__ __forceinline__ float lo_f(unsigned long long v) {
    return __uint_as_float((unsigned)(v & 0xffffffffull));
}
__device__ __forceinline__ float hi_f(unsigned long long v) {
    return __uint_as_float((unsigned)(v >> 32));
}

// ---------------------------------------------------------------------------
// conv1: 3x3, pad 1, 512->1024, fused BN + LeakyReLU(0.1).
// Block: 64 output channels x (8 rows x 32 cols) for one batch.
// Grid: (4 row tiles, 16 co tiles, 32 batches).
// Thread (256): ct = tid&7 -> 8 co (as 4 f32x2 pairs); pt = tid>>3 -> 8 pos.
// ---------------------------------------------------------------------------
__global__ __launch_bounds__(256, 2)
void conv1_bn_lrelu(const float* __restrict__ feat,
                    const float* __restrict__ w1,
                    const float* __restrict__ gamma,
                    const float* __restrict__ beta,
                    const float* __restrict__ mean,
                    const float* __restrict__ var) {
    __shared__ __align__(16) float2 sIn[8][10][34];   // input, duplicated {v,v}; halo'd
    __shared__ __align__(16) float  sW[8][9][80];     // [ci][kh*3+kw][co], pad 64->80

    const int b    = blockIdx.z;
    const int co0  = blockIdx.y * 64;
    const int row0 = blockIdx.x * 8;
    const int tid  = threadIdx.x;
    const int ct   = tid & 7;
    const int pt   = tid >> 3;
    const int r    = pt >> 2;          // 0..7 output row within tile
    const int cb   = (pt & 3) * 8;     // output col block (8 consecutive cols)

    unsigned long long acc[4][8];
#pragma unroll
    for (int j = 0; j < 4; j++)
#pragma unroll
        for (int c = 0; c < 8; c++) acc[j][c] = 0ull;

    const float* featb = feat + (size_t)b * CIN_ * NPOS_;

    for (int ci0 = 0; ci0 < CIN_; ci0 += 8) {
        // ---- load input tile (8 ci x 10 rows x 34 cols, zero-padded halo) ----
#pragma unroll
        for (int it = 0; it < 11; it++) {
            int i = tid + it * 256;
            if (i < 8 * 10 * 34) {
                int k   = i / 340;
                int rem = i - k * 340;
                int gr  = rem / 34;
                int gc  = rem - gr * 34;
                int gh  = row0 + gr - 1;
                int gw  = gc - 1;
                float v = 0.f;
                if ((unsigned)gh < 32u && (unsigned)gw < 32u)
                    v = featb[((ci0 + k) * S_ + gh) * S_ + gw];
                sIn[k][gr][gc] = make_float2(v, v);
            }
        }
        // ---- load weights (64 co x 8 ci x 9) ----
#pragma unroll
        for (int it = 0; it < 18; it++) {
            int i   = tid + it * 256;          // exactly 4608 = 18*256
            int co  = i / 72;
            int rem = i - co * 72;
            int k   = rem / 9;
            int kk  = rem - k * 9;
            sW[k][kk][co] =
                w1[((size_t)(co0 + co) * CIN_ + (ci0 + k)) * 9 + kk];
        }
        __syncthreads();

        // ---- compute ----
#pragma unroll 2
        for (int k = 0; k < 8; k++) {
#pragma unroll
            for (int kh = 0; kh < 3; kh++) {
                const unsigned long long* inrow =
                    reinterpret_cast<const unsigned long long*>(&sIn[k][r + kh][0]);
                unsigned long long iv[10];
#pragma unroll
                for (int i = 0; i < 10; i++) iv[i] = inrow[cb + i];
#pragma unroll
                for (int kw = 0; kw < 3; kw++) {
                    const int kk = kh * 3 + kw;
                    const ulonglong2* wp =
                        reinterpret_cast<const ulonglong2*>(&sW[k][kk][ct * 8]);
                    ulonglong2 w01 = wp[0];
                    ulonglong2 w23 = wp[1];
#pragma unroll
                    for (int c = 0; c < 8; c++) {
                        unsigned long long in2 = iv[kw + c];
                        ffma2(acc[0][c], w01.x, in2);
                        ffma2(acc[1][c], w01.y, in2);
                        ffma2(acc[2][c], w23.x, in2);
                        ffma2(acc[3][c], w23.y, in2);
                    }
                }
            }
        }
        __syncthreads();
    }

    // ---- epilogue: BN + leaky, vectorized stores ----
    float* outb = g_x + (size_t)b * CMID_ * NPOS_ + (size_t)(row0 + r) * S_ + cb;
#pragma unroll
    for (int j = 0; j < 4; j++) {
#pragma unroll
        for (int h = 0; h < 2; h++) {
            int co = co0 + ct * 8 + j * 2 + h;
            float sc = gamma[co] * rsqrtf(var[co] + 1e-5f);
            float sh = beta[co] - mean[co] * sc;
            float vals[8];
#pragma unroll
            for (int c = 0; c < 8; c++) {
                unsigned long long a = acc[j][c];
                float v = (h == 0 ? lo_f(a) : hi_f(a)) * sc + sh;
                vals[c] = v > 0.f ? v : 0.1f * v;
            }
            float* o = outb + (size_t)co * NPOS_;
            *reinterpret_cast<float4*>(o) =
                make_float4(vals[0], vals[1], vals[2], vals[3]);
            *reinterpret_cast<float4*>(o + 4) =
                make_float4(vals[4], vals[5], vals[6], vals[7]);
        }
    }
}

// ---------------------------------------------------------------------------
// conv2: 1x1, 1024 -> 425 (+bias). SGEMM per batch:
// preds[b][co][p] = sum_ci w2[co][ci] * x[b][ci][p] + b2[co]
// Tile 128(co) x 128(pos) x 8(K). Thread: 8 co (4 pairs) x 8 pos.
// ---------------------------------------------------------------------------
__global__ __launch_bounds__(256, 2)
void conv2_gemm(const float* __restrict__ w2, const float* __restrict__ b2) {
    __shared__ __align__(16) float  sA[8][132];      // [kk][co], padded
    __shared__ __align__(16) float2 sB[8][128];      // [kk][pos], duplicated {v,v}

    const int b   = blockIdx.z;
    const int co0 = blockIdx.y * 128;
    const int p0  = blockIdx.x * 128;
    const int tid = threadIdx.x;
    const int ct  = tid & 15;
    const int pt  = tid >> 4;

    unsigned long long acc[4][8];
#pragma unroll
    for (int j = 0; j < 4; j++)
#pragma unroll
        for (int c = 0; c < 8; c++) acc[j][c] = 0ull;

    const float* xb = g_x + (size_t)b * CMID_ * NPOS_;

    for (int ci0 = 0; ci0 < CMID_; ci0 += 8) {
        // sA: 1024 floats, one float4 per thread (coalesced along ci)
        {
            int co  = tid >> 1;
            int kk4 = (tid & 1) * 4;
            int cog = co0 + co;
            float4 v = make_float4(0.f, 0.f, 0.f, 0.f);
            if (cog < CO2_)
                v = *reinterpret_cast<const float4*>(
                    &w2[(size_t)cog * CMID_ + ci0 + kk4]);
            sA[kk4 + 0][co] = v.x;
            sA[kk4 + 1][co] = v.y;
            sA[kk4 + 2][co] = v.z;
            sA[kk4 + 3][co] = v.w;
        }
        // sB: 1024 floats, one float4 per thread (coalesced along pos)
        {
            int kk = tid >> 5;
            int pp = (tid & 31) * 4;
            float4 v = *reinterpret_cast<const float4*>(
                &xb[(size_t)(ci0 + kk) * NPOS_ + p0 + pp]);
            sB[kk][pp + 0] = make_float2(v.x, v.x);
            sB[kk][pp + 1] = make_float2(v.y, v.y);
            sB[kk][pp + 2] = make_float2(v.z, v.z);
            sB[kk][pp + 3] = make_float2(v.w, v.w);
        }
        __syncthreads();

#pragma unroll
        for (int kk = 0; kk < 8; kk++) {
            const ulonglong2* wp =
                reinterpret_cast<const ulonglong2*>(&sA[kk][ct * 8]);
            ulonglong2 w01 = wp[0];
            ulonglong2 w23 = wp[1];
            const unsigned long long* inrow =
                reinterpret_cast<const unsigned long long*>(&sB[kk][pt * 8]);
#pragma unroll
            for (int c = 0; c < 8; c++) {
                unsigned long long in2 = inrow[c];
                ffma2(acc[0][c], w01.x, in2);
                ffma2(acc[1][c], w01.y, in2);
                ffma2(acc[2][c], w23.x, in2);
                ffma2(acc[3][c], w23.y, in2);
            }
        }
        __syncthreads();
    }

    // epilogue: bias + store (guard co < 425)
#pragma unroll
    for (int j = 0; j < 4; j++) {
#pragma unroll
        for (int h = 0; h < 2; h++) {
            int co = co0 + ct * 8 + j * 2 + h;
            if (co < CO2_) {
                float bias = b2[co];
                float vals[8];
#pragma unroll
                for (int c = 0; c < 8; c++) {
                    unsigned long long a = acc[j][c];
                    vals[c] = (h == 0 ? lo_f(a) : hi_f(a)) + bias;
                }
                float* o = g_preds + ((size_t)b * CO2_ + co) * NPOS_ + p0 + pt * 8;
                *reinterpret_cast<float4*>(o) =
                    make_float4(vals[0], vals[1], vals[2], vals[3]);
                *reinterpret_cast<float4*>(o + 4) =
                    make_float4(vals[4], vals[5], vals[6], vals[7]);
            }
        }
    }
}

// ---------------------------------------------------------------------------
// decode: one thread per (b, p, a). Online softmax-max + argmax.
// Output layout: [out5 (32*5120*5 f32)] then [labels (32*5120) as f32].
// ---------------------------------------------------------------------------
__global__ void decode_kernel(float* __restrict__ out) {
    int t = blockIdx.x * 256 + threadIdx.x;      // 163840 total
    int p  = t & 1023;
    int ba = t >> 10;
    int a  = ba % 5;
    int b  = ba / 5;

    const float* pr = g_preds + ((size_t)b * CO2_ + a * 85) * NPOS_ + p;
    float tx = pr[0 * NPOS_];
    float ty = pr[1 * NPOS_];
    float tw = pr[2 * NPOS_];
    float th = pr[3 * NPOS_];
    float to = pr[4 * NPOS_];

    float m = -1e30f, ssum = 0.f;
    int arg = 0;
#pragma unroll 4
    for (int j = 0; j < 80; j++) {
        float l = pr[(5 + j) * NPOS_];
        if (l > m) {
            ssum = ssum * expf(m - l) + 1.f;
            m = l;
            arg = j;
        } else {
            ssum += expf(l - m);
        }
    }

    float obj   = 1.f / (1.f + expf(-to));
    float score = obj / ssum;                // obj * max(softmax)
    float bx = 1.f / (1.f + expf(-tx));
    float by = 1.f / (1.f + expf(-ty));
    float bw = expf(fminf(tw, 8.f));
    float bh = expf(fminf(th, 8.f));

    float sx = (float)(p & 31);
    float sy = (float)(p >> 5);
    float cx = (bx + sx) * 32.f;
    float cy = (by + sy) * 32.f;
    float pw = c_anc_w[a] * bw;              // (anchor/32)*exp*32
    float ph = c_anc_h[a] * bh;

    float x1 = fminf(fmaxf(cx - 0.5f * pw, 0.f), 1023.f);
    float y1 = fminf(fmaxf(cy - 0.5f * ph, 0.f), 1023.f);
    float x2 = fminf(fmaxf(cx + 0.5f * pw, 0.f), 1023.f);
    float y2 = fminf(fmaxf(cy + 0.5f * ph, 0.f), 1023.f);

    size_t n = (size_t)b * 5120 + (size_t)p * 5 + a;
    float* o5 = out + n * 5;
    o5[0] = x1;
    o5[1] = y1;
    o5[2] = x2;
    o5[3] = y2;
    o5[4] = score;
    out[(size_t)819200 + n] = (float)arg;
}

// ---------------------------------------------------------------------------
extern "C" void kernel_launch(void* const* d_in, const int* in_sizes, int n_in,
                              void* d_out, int out_size) {
    const float* feat  = (const float*)d_in[0];
    const float* w1    = (const float*)d_in[1];
    const float* gam   = (const float*)d_in[2];
    const float* bet   = (const float*)d_in[3];
    const float* mean  = (const float*)d_in[4];
    const float* var   = (const float*)d_in[5];
    const float* w2    = (const float*)d_in[6];
    const float* b2    = (const float*)d_in[7];
    float* out = (float*)d_out;

    conv1_bn_lrelu<<<dim3(4, 16, 32), 256>>>(feat, w1, gam, bet, mean, var);
    conv2_gemm<<<dim3(8, 4, 32), 256>>>(w2, b2);
    decode_kernel<<<640, 256>>>(out);
}

// round 4
// speedup vs baseline: 3.0996x; 3.0877x over previous
#include <cuda_runtime.h>
#include <cuda_fp16.h>
#include <cstdint>

#define DI __device__ __forceinline__

static constexpr int CIN = 512, CMID = 1024, CO2 = 425, NPOS = 1024;

// ---------------- device scratch (fp16 hi/lo splits) ----------------
__device__ __half g_a_h[(size_t)32 * NPOS * CIN];
__device__ __half g_a_l[(size_t)32 * NPOS * CIN];
__device__ __half g_x_h[(size_t)32 * NPOS * CMID];
__device__ __half g_x_l[(size_t)32 * NPOS * CMID];
__device__ __half g_w1_h[(size_t)9 * CMID * CIN];
__device__ __half g_w1_l[(size_t)9 * CMID * CIN];
__device__ __half g_w2_h[(size_t)512 * CMID];
__device__ __half g_w2_l[(size_t)512 * CMID];
__device__ float  g_preds[(size_t)32 * NPOS * 512];

__constant__ float c_anc_w[5] = {42.f, 98.f, 180.f, 300.f, 400.f};
__constant__ float c_anc_h[5] = {45.f, 130.f, 260.f, 180.f, 400.f};

// ---------------- PTX helpers (all baseline sm_80-class) ----------------
DI uint32_t smem_u32(const void* p) {
    uint32_t a;
    asm("{ .reg .u64 t; cvta.to.shared.u64 t, %1; cvt.u32.u64 %0, t; }" : "=r"(a) : "l"(p));
    return a;
}
DI void cp16(uint32_t dst, const void* src, uint32_t nbytes) {
    asm volatile("cp.async.cg.shared.global [%0], [%1], 16, %2;"
                 :: "r"(dst), "l"(src), "r"(nbytes) : "memory");
}
DI void cp_commit() { asm volatile("cp.async.commit_group;" ::: "memory"); }
template <int N> DI void cp_wait() {
    asm volatile("cp.async.wait_group %0;" :: "n"(N) : "memory");
}
DI void ldm4(uint32_t a, uint32_t& r0, uint32_t& r1, uint32_t& r2, uint32_t& r3) {
    asm volatile("ldmatrix.sync.aligned.m8n8.x4.shared.b16 {%0,%1,%2,%3}, [%4];"
                 : "=r"(r0), "=r"(r1), "=r"(r2), "=r"(r3) : "r"(a));
}
DI void mma16816(float* c, const uint32_t* a, const uint32_t* b) {
    asm volatile(
        "mma.sync.aligned.m16n8k16.row.col.f32.f16.f16.f32 "
        "{%0,%1,%2,%3},{%4,%5,%6,%7},{%8,%9},{%0,%1,%2,%3};"
        : "+f"(c[0]), "+f"(c[1]), "+f"(c[2]), "+f"(c[3])
        : "r"(a[0]), "r"(a[1]), "r"(a[2]), "r"(a[3]), "r"(b[0]), "r"(b[1]));
}
DI uint32_t swz(uint32_t byte_off, int rl) {  // XOR bit4 with bit2 of row index
    return byte_off ^ ((rl & 4) << 2);
}

// ---------------- prep kernels ----------------
__global__ void prep_x(const float* __restrict__ feat) {
    __shared__ float t[32][33];
    const int r = blockIdx.x, cit = blockIdx.y, b = blockIdx.z;
    const int col = threadIdx.x & 31, row8 = threadIdx.x >> 5;
#pragma unroll
    for (int it = 0; it < 4; it++) {
        int ci_l = row8 + it * 8;
        t[ci_l][col] = feat[(((size_t)b * CIN + cit * 32 + ci_l) * 32 + r) * 32 + col];
    }
    __syncthreads();
    const int ci = threadIdx.x & 31;
#pragma unroll
    for (int it = 0; it < 4; it++) {
        int cc = (threadIdx.x >> 5) + it * 8;
        float v = t[ci][cc];
        __half hi = __float2half_rn(v);
        __half lo = __float2half_rn(v - __half2float(hi));
        size_t o = ((size_t)b * NPOS + r * 32 + cc) * CIN + cit * 32 + ci;
        g_a_h[o] = hi;
        g_a_l[o] = lo;
    }
}
__global__ void prep_w1(const float* __restrict__ w1) {
    int t = blockIdx.x * 256 + threadIdx.x;  // 1024*512
    int co = t >> 9, ci = t & 511;
#pragma unroll
    for (int kk = 0; kk < 9; kk++) {
        float v = w1[((size_t)co * CIN + ci) * 9 + kk];
        __half hi = __float2half_rn(v);
        __half lo = __float2half_rn(v - __half2float(hi));
        size_t o = ((size_t)kk * CMID + co) * CIN + ci;
        g_w1_h[o] = hi;
        g_w1_l[o] = lo;
    }
}
__global__ void prep_w2(const float* __restrict__ w2) {
    int t = blockIdx.x * 256 + threadIdx.x;  // 512*1024
    int co = t >> 10, ci = t & 1023;
    float v = (co < CO2) ? w2[(size_t)co * CMID + ci] : 0.f;
    __half hi = __float2half_rn(v);
    __half lo = __float2half_rn(v - __half2float(hi));
    g_w2_h[t] = hi;
    g_w2_l[t] = lo;
}

// ---------------- conv1: implicit 3x3 conv, fp16-split mma.sync -------------
// Block: M=256 pos (8 out rows x 32 cols) x N=128 co; 512 thr (16 warps 4x4).
static constexpr int C1_IN_SPLIT = 10880;       // 10*34*16*2
static constexpr int C1_WOFF = 21760;           // input total (2 splits)
static constexpr int C1_STAGE = 21760 + 73728;  // 95488
static constexpr int C1_SMEM = 2 * C1_STAGE + 1024;

__global__ void __launch_bounds__(512, 1)
conv1_mma(const float* __restrict__ gamma, const float* __restrict__ beta,
          const float* __restrict__ mean, const float* __restrict__ var) {
    extern __shared__ __align__(16) char smem[];
    const uint32_t sb = smem_u32(smem);
    const int tid = threadIdx.x, lane = tid & 31, wid = tid >> 5;
    const int b = blockIdx.z, co0 = blockIdx.y * 128, row0 = blockIdx.x * 8;
    float* s_sc = (float*)(smem + 2 * C1_STAGE);
    float* s_sh = s_sc + 128;
    if (tid < 128) {
        float sc = gamma[co0 + tid] * rsqrtf(var[co0 + tid] + 1e-5f);
        s_sc[tid] = sc;
        s_sh[tid] = beta[co0 + tid] - mean[co0 + tid] * sc;
    }
    const int warp_m0 = (wid >> 2) * 64, warp_n0 = (wid & 3) * 32;
    const int aro = ((lane >> 3) & 1) * 8 + (lane & 7);
    const int ahalf = lane >> 4;
    int Lb[4];
#pragma unroll
    for (int mf = 0; mf < 4; mf++) {
        int m = warp_m0 + mf * 16 + aro;
        Lb[mf] = (m >> 5) * 34 + (m & 31);
    }
    const int bco = ((lane >> 4) << 3) + (lane & 7);
    const int bhalf = (lane >> 3) & 1;
    const uint32_t bbase = swz((uint32_t)(bco * 32 + bhalf * 16), bco);

    float acc[4][4][4];
#pragma unroll
    for (int i = 0; i < 4; i++)
#pragma unroll
        for (int j = 0; j < 4; j++)
#pragma unroll
            for (int k = 0; k < 4; k++) acc[i][j][k] = 0.f;

    auto load_stage = [&](int s, int ci0) {
        uint32_t st = sb + s * C1_STAGE;
        // input: 2 splits x 10 rows x 34 cols x 2 halves = 1360 x 16B
#pragma unroll
        for (int it = 0; it < 3; it++) {
            int u = tid + it * 512;
            if (u < 1360) {
                int split = u >= 680;
                int r2 = u - split * 680;
                int i = r2 / 68;
                int r3 = r2 - i * 68;
                int j = r3 >> 1, half = r3 & 1;
                int ri = row0 + i - 1, cix = j - 1;
                bool ok = (unsigned)ri < 32u && (unsigned)cix < 32u;
                const __half* g = split ? g_a_l : g_a_h;
                const __half* src =
                    ok ? g + (((size_t)b * NPOS + ri * 32 + cix) * CIN + ci0 + half * 8) : g;
                int rl = i * 34 + j;
                uint32_t d = st + split * C1_IN_SPLIT +
                             swz((uint32_t)(rl * 32 + half * 16), rl);
                cp16(d, src, ok ? 16u : 0u);
            }
        }
        // weights: 9 kk x 2 splits x 128 co x 2 halves = 4608 x 16B
#pragma unroll
        for (int it = 0; it < 9; it++) {
            int u = tid + it * 512;
            int kk = u >> 9;
            int r2 = u & 511;
            int split = r2 >> 8;
            int r3 = r2 & 255;
            int co = r3 >> 1, half = r3 & 1;
            const __half* g = split ? g_w1_l : g_w1_h;
            const __half* src = g + (((size_t)kk * CMID + co0 + co) * CIN + ci0 + half * 8);
            uint32_t d = st + C1_WOFF + (kk * 2 + split) * 4096 +
                         swz((uint32_t)(co * 32 + half * 16), co);
            cp16(d, src, 16u);
        }
    };

    load_stage(0, 0);
    cp_commit();

    for (int ch = 0; ch < 32; ch++) {
        if (ch < 31) {
            load_stage((ch + 1) & 1, (ch + 1) * 16);
            cp_commit();
            cp_wait<1>();
        } else {
            cp_wait<0>();
        }
        __syncthreads();
        uint32_t st = sb + (ch & 1) * C1_STAGE;
        uint32_t areg[4][4], breg[4][2];
#pragma unroll
        for (int kk = 0; kk < 9; kk++) {
            const int D = (kk / 3) * 34 + (kk % 3);
            auto lda = [&](int split) {
                uint32_t base = st + split * C1_IN_SPLIT;
#pragma unroll
                for (int mf = 0; mf < 4; mf++) {
                    int rl = Lb[mf] + D;
                    uint32_t ad = base + swz((uint32_t)(rl * 32 + ahalf * 16), rl);
                    ldm4(ad, areg[mf][0], areg[mf][1], areg[mf][2], areg[mf][3]);
                }
            };
            auto ldb = [&](int split) {
                uint32_t base = st + C1_WOFF + (kk * 2 + split) * 4096 + bbase;
#pragma unroll
                for (int np = 0; np < 2; np++) {
                    uint32_t r0, r1, r2, r3;
                    ldm4(base + (uint32_t)((warp_n0 + np * 16) * 32), r0, r1, r2, r3);
                    breg[np * 2][0] = r0;
                    breg[np * 2][1] = r1;
                    breg[np * 2 + 1][0] = r2;
                    breg[np * 2 + 1][1] = r3;
                }
            };
            auto domma = [&]() {
#pragma unroll
                for (int mf = 0; mf < 4; mf++)
#pragma unroll
                    for (int nf = 0; nf < 4; nf++) mma16816(acc[mf][nf], areg[mf], breg[nf]);
            };
            lda(0); ldb(0); domma();   // Ah*Bh
            lda(1); domma();           // Al*Bh
            ldb(1); lda(0); domma();   // Ah*Bl
        }
        __syncthreads();
    }

    // epilogue: BN + leaky, write fp16 hi/lo splits for conv2
    const int gq = lane >> 2, t4 = lane & 3;
#pragma unroll
    for (int mf = 0; mf < 4; mf++) {
#pragma unroll
        for (int nf = 0; nf < 4; nf++) {
            int n = warp_n0 + nf * 8 + t4 * 2;
            float sc0 = s_sc[n], sc1 = s_sc[n + 1];
            float sh0 = s_sh[n], sh1 = s_sh[n + 1];
#pragma unroll
            for (int rr = 0; rr < 2; rr++) {
                int m = warp_m0 + mf * 16 + gq + rr * 8;
                float v0 = acc[mf][nf][rr * 2] * sc0 + sh0;
                float v1 = acc[mf][nf][rr * 2 + 1] * sc1 + sh1;
                v0 = v0 > 0.f ? v0 : 0.1f * v0;
                v1 = v1 > 0.f ? v1 : 0.1f * v1;
                __half h0 = __float2half_rn(v0), h1 = __float2half_rn(v1);
                __half l0 = __float2half_rn(v0 - __half2float(h0));
                __half l1 = __float2half_rn(v1 - __half2float(h1));
                size_t idx =
                    ((size_t)b * NPOS + blockIdx.x * 256 + m) * CMID + co0 + n;
                *(__half2*)(g_x_h + idx) = __halves2half2(h0, h1);
                *(__half2*)(g_x_l + idx) = __halves2half2(l0, l1);
            }
        }
    }
}

// ---------------- conv2: 1x1 GEMM, fp16-split mma.sync ----------------------
static constexpr int C2_IN_SPLIT = 8192;        // 256*16*2
static constexpr int C2_WOFF = 16384;
static constexpr int C2_STAGE = 16384 + 8192;   // 24576
static constexpr int C2_SMEM = 2 * C2_STAGE + 512;

__global__ void __launch_bounds__(512, 1)
conv2_mma(const float* __restrict__ b2) {
    extern __shared__ __align__(16) char smem[];
    const uint32_t sb = smem_u32(smem);
    const int tid = threadIdx.x, lane = tid & 31, wid = tid >> 5;
    const int b = blockIdx.z, co0 = blockIdx.y * 128, m0 = blockIdx.x * 256;
    float* s_bias = (float*)(smem + 2 * C2_STAGE);
    if (tid < 128) s_bias[tid] = (co0 + tid < CO2) ? b2[co0 + tid] : 0.f;

    const int warp_m0 = (wid >> 2) * 64, warp_n0 = (wid & 3) * 32;
    const int aro = ((lane >> 3) & 1) * 8 + (lane & 7);
    const int ahalf = lane >> 4;
    const int bco = ((lane >> 4) << 3) + (lane & 7);
    const int bhalf = (lane >> 3) & 1;
    const uint32_t bbase = swz((uint32_t)(bco * 32 + bhalf * 16), bco);

    float acc[4][4][4];
#pragma unroll
    for (int i = 0; i < 4; i++)
#pragma unroll
        for (int j = 0; j < 4; j++)
#pragma unroll
            for (int k = 0; k < 4; k++) acc[i][j][k] = 0.f;

    auto load_stage = [&](int s, int ci0) {
        uint32_t st = sb + s * C2_STAGE;
#pragma unroll
        for (int it = 0; it < 2; it++) {  // input: 2x256x2 = 1024 units
            int u = tid + it * 512;
            int split = u >> 9;
            int r2 = u & 511;
            int m = r2 >> 1, half = r2 & 1;
            const __half* g = split ? g_x_l : g_x_h;
            const __half* src = g + (((size_t)b * NPOS + m0 + m) * CMID + ci0 + half * 8);
            uint32_t d = st + split * C2_IN_SPLIT + swz((uint32_t)(m * 32 + half * 16), m);
            cp16(d, src, 16u);
        }
        {  // weights: 2x128x2 = 512 units
            int u = tid;
            int split = u >> 8;
            int r2 = u & 255;
            int co = r2 >> 1, half = r2 & 1;
            const __half* g = split ? g_w2_l : g_w2_h;
            const __half* src = g + ((size_t)(co0 + co) * CMID + ci0 + half * 8);
            uint32_t d = st + C2_WOFF + split * 4096 +
                         swz((uint32_t)(co * 32 + half * 16), co);
            cp16(d, src, 16u);
        }
    };

    load_stage(0, 0);
    cp_commit();

    for (int ch = 0; ch < 64; ch++) {
        if (ch < 63) {
            load_stage((ch + 1) & 1, (ch + 1) * 16);
            cp_commit();
            cp_wait<1>();
        } else {
            cp_wait<0>();
        }
        __syncthreads();
        uint32_t st = sb + (ch & 1) * C2_STAGE;
        uint32_t areg[4][4], breg[4][2];
        auto lda = [&](int split) {
            uint32_t base = st + split * C2_IN_SPLIT;
#pragma unroll
            for (int mf = 0; mf < 4; mf++) {
                int m = warp_m0 + mf * 16 + aro;
                uint32_t ad = base + swz((uint32_t)(m * 32 + ahalf * 16), m);
                ldm4(ad, areg[mf][0], areg[mf][1], areg[mf][2], areg[mf][3]);
            }
        };
        auto ldb = [&](int split) {
            uint32_t base = st + C2_WOFF + split * 4096 + bbase;
#pragma unroll
            for (int np = 0; np < 2; np++) {
                uint32_t r0, r1, r2, r3;
                ldm4(base + (uint32_t)((warp_n0 + np * 16) * 32), r0, r1, r2, r3);
                breg[np * 2][0] = r0;
                breg[np * 2][1] = r1;
                breg[np * 2 + 1][0] = r2;
                breg[np * 2 + 1][1] = r3;
            }
        };
        auto domma = [&]() {
#pragma unroll
            for (int mf = 0; mf < 4; mf++)
#pragma unroll
                for (int nf = 0; nf < 4; nf++) mma16816(acc[mf][nf], areg[mf], breg[nf]);
        };
        lda(0); ldb(0); domma();
        lda(1); domma();
        ldb(1); lda(0); domma();
        __syncthreads();
    }

    const int gq = lane >> 2, t4 = lane & 3;
#pragma unroll
    for (int mf = 0; mf < 4; mf++) {
#pragma unroll
        for (int nf = 0; nf < 4; nf++) {
            int n = warp_n0 + nf * 8 + t4 * 2;
            float b0 = s_bias[n], b1 = s_bias[n + 1];
#pragma unroll
            for (int rr = 0; rr < 2; rr++) {
                int m = warp_m0 + mf * 16 + gq + rr * 8;
                float v0 = acc[mf][nf][rr * 2] + b0;
                float v1 = acc[mf][nf][rr * 2 + 1] + b1;
                size_t idx = ((size_t)b * NPOS + m0 + m) * 512 + co0 + n;
                *(float2*)(g_preds + idx) = make_float2(v0, v1);
            }
        }
    }
}

// ---------------- decode ----------------
__global__ void decode_kernel(float* __restrict__ out) {
    int t = blockIdx.x * 256 + threadIdx.x;
    int p = t & 1023, ba = t >> 10, a = ba % 5, b = ba / 5;
    const float* pr = g_preds + ((size_t)b * NPOS + p) * 512 + a * 85;
    float tx = pr[0], ty = pr[1], tw = pr[2], th = pr[3], to = pr[4];
    float m = -1e30f, ssum = 0.f;
    int arg = 0;
#pragma unroll 4
    for (int j = 0; j < 80; j++) {
        float l = pr[5 + j];
        if (l > m) { ssum = ssum * expf(m - l) + 1.f; m = l; arg = j; }
        else        ssum += expf(l - m);
    }
    float obj = 1.f / (1.f + expf(-to));
    float score = obj / ssum;
    float bx = 1.f / (1.f + expf(-tx));
    float by = 1.f / (1.f + expf(-ty));
    float bw = expf(fminf(tw, 8.f));
    float bh = expf(fminf(th, 8.f));
    float cx = (bx + (float)(p & 31)) * 32.f;
    float cy = (by + (float)(p >> 5)) * 32.f;
    float pw = c_anc_w[a] * bw, ph = c_anc_h[a] * bh;
    float x1 = fminf(fmaxf(cx - 0.5f * pw, 0.f), 1023.f);
    float y1 = fminf(fmaxf(cy - 0.5f * ph, 0.f), 1023.f);
    float x2 = fminf(fmaxf(cx + 0.5f * pw, 0.f), 1023.f);
    float y2 = fminf(fmaxf(cy + 0.5f * ph, 0.f), 1023.f);
    size_t n = (size_t)b * 5120 + (size_t)p * 5 + a;
    float* o5 = out + n * 5;
    o5[0] = x1; o5[1] = y1; o5[2] = x2; o5[3] = y2; o5[4] = score;
    out[(size_t)819200 + n] = (float)arg;
}

// ---------------- host ----------------
extern "C" void kernel_launch(void* const* d_in, const int* in_sizes, int n_in,
                              void* d_out, int out_size) {
    const float* feat = (const float*)d_in[0];
    const float* w1   = (const float*)d_in[1];
    const float* gam  = (const float*)d_in[2];
    const float* bet  = (const float*)d_in[3];
    const float* mean = (const float*)d_in[4];
    const float* var  = (const float*)d_in[5];
    const float* w2   = (const float*)d_in[6];
    const float* b2   = (const float*)d_in[7];
    float* out = (float*)d_out;

    static bool attr_done = false;
    if (!attr_done) {
        cudaFuncSetAttribute(conv1_mma, cudaFuncAttributeMaxDynamicSharedMemorySize, C1_SMEM);
        cudaFuncSetAttribute(conv2_mma, cudaFuncAttributeMaxDynamicSharedMemorySize, C2_SMEM);
        attr_done = true;
    }

    prep_x<<<dim3(32, 16, 32), 256>>>(feat);
    prep_w1<<<2048, 256>>>(w1);
    prep_w2<<<2048, 256>>>(w2);
    conv1_mma<<<dim3(4, 8, 32), 512, C1_SMEM>>>(gam, bet, mean, var);
    conv2_mma<<<dim3(4, 4, 32), 512, C2_SMEM>>>(b2);
    decode_kernel<<<640, 256>>>(out);
}